// round 9
// baseline (speedup 1.0000x reference)
#include <cuda_runtime.h>
#include <math.h>
#include <stdint.h>

#define THREADS 256
#define WARPS (THREADS / 32)              // 8
#define CHUNK_ROWS 32
#define CHUNK_FLOATS (CHUNK_ROWS * 7)     // 224
#define ITERS 4
#define STAGES 2
#define CHUNKS_PER_BLOCK (WARPS * ITERS)  // 32

struct Smem {
    float buf[STAGES][WARPS][2][CHUNK_FLOATS];  // [stage][warp][0=rep,1=emo]; 28672 B
    float M[56];                                // W_Q^T @ W_K, padded 7x8
    float CW[8];                                // colsum(W_D)[0..6], [7]=sum(b_D)
};

// Issue the cp.asyncs for chunk c into [stage][wid] (guarded), then ALWAYS commit
// (empty commit groups keep per-lane group counting uniform).
__device__ __forceinline__ void prefetch_chunk(Smem* sm, int stage, int wid, int lane,
                                               const float* __restrict__ rep,
                                               const float* __restrict__ emo,
                                               long long c, long long nrows)
{
    if ((c + 1) * CHUNK_ROWS <= nrows && lane < 28) {
        const float4* gr = (const float4*)(rep + c * CHUNK_FLOATS);
        const float4* ge = (const float4*)(emo + c * CHUNK_FLOATS);
        uint32_t dr = (uint32_t)__cvta_generic_to_shared(&sm->buf[stage][wid][0][0]);
        uint32_t de = (uint32_t)__cvta_generic_to_shared(&sm->buf[stage][wid][1][0]);
        asm volatile("cp.async.cg.shared.global [%0], [%1], 16;" :: "r"(dr + lane * 16),       "l"(gr + lane)      : "memory");
        asm volatile("cp.async.cg.shared.global [%0], [%1], 16;" :: "r"(dr + 448 + lane * 16), "l"(gr + 28 + lane) : "memory");
        asm volatile("cp.async.cg.shared.global [%0], [%1], 16;" :: "r"(de + lane * 16),       "l"(ge + lane)      : "memory");
        asm volatile("cp.async.cg.shared.global [%0], [%1], 16;" :: "r"(de + 448 + lane * 16), "l"(ge + 28 + lane) : "memory");
    }
    asm volatile("cp.async.commit_group;" ::: "memory");
}

__global__ __launch_bounds__(THREADS, 6)
void emotion_kernel(const float* __restrict__ rep,
                    const float* __restrict__ emo,
                    const float* __restrict__ WQ,
                    const float* __restrict__ WK,
                    const float* __restrict__ WD,
                    const float* __restrict__ bD,
                    float* __restrict__ out,
                    int nrows)
{
    __shared__ Smem sm;

    const int tid  = threadIdx.x;
    const int wid  = tid >> 5;
    const int lane = tid & 31;
    const long long N = nrows;
    const long long c0 = (long long)blockIdx.x * CHUNKS_PER_BLOCK + wid;

    // ---- prime the per-warp pipeline (2 stages) ----
    prefetch_chunk(&sm, 0, wid, lane, rep, emo, c0 + 0 * WARPS, N);
    prefetch_chunk(&sm, 1, wid, lane, rep, emo, c0 + 1 * WARPS, N);

    // ---- per-block constants (tiny, L2-hit; overlaps the async loads) ----
    if (tid < 49) {
        int j = tid / 7, k = tid % 7;
        float acc = 0.f;
        #pragma unroll
        for (int i = 0; i < 7; ++i) acc = fmaf(WQ[i * 7 + j], WK[i * 7 + k], acc);
        sm.M[j * 8 + k] = acc;
    } else if (tid < 56) {
        int k = tid - 49;
        float acc = 0.f;
        #pragma unroll
        for (int j = 0; j < 7; ++j) acc += WD[j * 7 + k];
        sm.CW[k] = acc;
    } else if (tid == 56) {
        float acc = 0.f;
        #pragma unroll
        for (int i = 0; i < 7; ++i) acc += bD[i];
        sm.CW[7] = acc;
    }
    __syncthreads();   // constants visible; the ONLY block-wide barrier

    const float4* sM4  = (const float4*)sm.M;
    const float4* sCW4 = (const float4*)sm.CW;
    const float4 cc0 = sCW4[0];
    const float4 cc1 = sCW4[1];
    const float cw[7] = {cc0.x, cc0.y, cc0.z, cc0.w, cc1.x, cc1.y, cc1.z};
    const float cb = cc1.w;

    #pragma unroll
    for (int i = 0; i < ITERS; ++i) {
        const long long c = c0 + (long long)i * WARPS;
        const int s = i & 1;

        asm volatile("cp.async.wait_group 1;" ::: "memory");
        __syncwarp();   // every lane's groups drained -> whole chunk visible

        const bool full = (c + 1) * CHUNK_ROWS <= N;
        if (full) {
            float* rb = &sm.buf[s][wid][0][0];
            float* eb = &sm.buf[s][wid][1][0];
            const int base = lane * 7;           // lane-private row (stride-7: conflict-free)

            float r[7], e[7];
            #pragma unroll
            for (int j = 0; j < 7; ++j) { r[j] = rb[base + j]; e[j] = eb[base + j]; }

            float t[7];
            #pragma unroll
            for (int k = 0; k < 7; ++k) t[k] = 0.f;
            #pragma unroll
            for (int j = 0; j < 7; ++j) {
                float4 m0 = sM4[j * 2 + 0];
                float4 m1 = sM4[j * 2 + 1];
                float ej = e[j];
                t[0] = fmaf(ej, m0.x, t[0]);
                t[1] = fmaf(ej, m0.y, t[1]);
                t[2] = fmaf(ej, m0.z, t[2]);
                t[3] = fmaf(ej, m0.w, t[3]);
                t[4] = fmaf(ej, m1.x, t[4]);
                t[5] = fmaf(ej, m1.y, t[5]);
                t[6] = fmaf(ej, m1.z, t[6]);
            }
            // softmax without max-subtraction (|raw| << 88: exp safe)
            float p[7], sum = 0.f;
            #pragma unroll
            for (int k = 0; k < 7; ++k) { p[k] = __expf(r[k] * t[k]); sum += p[k]; }
            float inv = __fdividef(1.f, sum);

            float o[7];
            #pragma unroll
            for (int k = 0; k < 7; ++k) {
                float sv = p[k] * inv;
                float s3 = sv * sv * sv;
                float d  = fmaf(s3, cw[k], cb);
                d = fminf(1.f, fmaxf(-1.f, d));
                o[k] = r[k] + d;
            }

            // stage output into own (already-consumed) rep slot, then coalesced STG
            #pragma unroll
            for (int j = 0; j < 7; ++j) rb[base + j] = o[j];
            __syncwarp();
            if (lane < 28) {
                float4 v0 = ((const float4*)rb)[lane];
                float4 v1 = ((const float4*)rb)[28 + lane];
                float4* go = (float4*)(out + c * CHUNK_FLOATS);
                go[lane] = v0;
                go[28 + lane] = v1;
            }
        } else {
            // rare tail chunk: direct global path, no smem
            long long row = c * CHUNK_ROWS + lane;
            if (row < N) {
                float r[7], e[7];
                #pragma unroll
                for (int j = 0; j < 7; ++j) { r[j] = rep[row * 7 + j]; e[j] = emo[row * 7 + j]; }
                float t[7];
                #pragma unroll
                for (int k = 0; k < 7; ++k) t[k] = 0.f;
                #pragma unroll
                for (int j = 0; j < 7; ++j) {
                    float ej = e[j];
                    #pragma unroll
                    for (int k = 0; k < 7; ++k) t[k] = fmaf(ej, sm.M[j * 8 + k], t[k]);
                }
                float p[7], sum = 0.f;
                #pragma unroll
                for (int k = 0; k < 7; ++k) { p[k] = __expf(r[k] * t[k]); sum += p[k]; }
                float inv = __fdividef(1.f, sum);
                #pragma unroll
                for (int k = 0; k < 7; ++k) {
                    float sv = p[k] * inv;
                    float s3 = sv * sv * sv;
                    float d  = fmaf(s3, cw[k], cb);
                    d = fminf(1.f, fmaxf(-1.f, d));
                    out[row * 7 + k] = r[k] + d;
                }
            }
        }

        // refill this stage for chunk i+2 (skip past block's range via sentinel; commit always)
        long long cn = (i + 2 < ITERS) ? (c0 + (long long)(i + 2) * WARPS) : ((long long)1 << 60);
        prefetch_chunk(&sm, s, wid, lane, rep, emo, cn, N);
    }
}

extern "C" void kernel_launch(void* const* d_in, const int* in_sizes, int n_in,
                              void* d_out, int out_size)
{
    const float* rep = (const float*)d_in[0];
    const float* emo = (const float*)d_in[1];
    const float* WQ  = (const float*)d_in[2];
    const float* WK  = (const float*)d_in[3];
    const float* WD  = (const float*)d_in[4];
    const float* bD  = (const float*)d_in[5];
    float* out = (float*)d_out;

    int nrows = in_sizes[0] / 7;
    long long nchunks = ((long long)nrows + CHUNK_ROWS - 1) / CHUNK_ROWS;
    int grid = (int)((nchunks + CHUNKS_PER_BLOCK - 1) / CHUNKS_PER_BLOCK);

    emotion_kernel<<<grid, THREADS>>>(rep, emo, WQ, WK, WD, bD, out, nrows);
}

// round 12
// speedup vs baseline: 1.4893x; 1.4893x over previous
#include <cuda_runtime.h>
#include <math.h>
#include <stdint.h>

#define THREADS 256
#define WARPS 8
#define WARP_ROWS 128
#define WARP_FLOATS (WARP_ROWS * 7)     // 896
#define WARP_BYTES (WARP_FLOATS * 4)    // 3584
#define ROWS_PER_BLOCK (WARPS * WARP_ROWS)  // 1024

struct Smem {
    float rep[WARPS][WARP_FLOATS];      // per-warp in-tile; reused as out-tile
    float emo[WARPS][WARP_FLOATS];
    float M[64];                        // W_Q^T @ W_K, 49 used (8x8 padded)
    float CW[8];                        // colsum(W_D)[0..6], [7]=sum(b_D)
    unsigned long long mbar[WARPS];
};
#define SMEM_BYTES ((int)sizeof(Smem))

__global__ __launch_bounds__(THREADS)
void emotion_kernel(const float* __restrict__ rep,
                    const float* __restrict__ emo,
                    const float* __restrict__ WQ,
                    const float* __restrict__ WK,
                    const float* __restrict__ WD,
                    const float* __restrict__ bD,
                    float* __restrict__ out,
                    int nrows)
{
    extern __shared__ __align__(16) char smem_raw[];
    Smem& sm = *(Smem*)smem_raw;

    const int tid  = threadIdx.x;
    const int wid  = tid >> 5;
    const int lane = tid & 31;

    const long long row0 = (long long)blockIdx.x * ROWS_PER_BLOCK + (long long)wid * WARP_ROWS;
    const bool full = (row0 + WARP_ROWS) <= (long long)nrows;

    const uint32_t a_mbar = (uint32_t)__cvta_generic_to_shared(&sm.mbar[wid]);
    const uint32_t a_rep  = (uint32_t)__cvta_generic_to_shared(&sm.rep[wid][0]);
    const uint32_t a_emo  = (uint32_t)__cvta_generic_to_shared(&sm.emo[wid][0]);

    // ---- warp-private mbarrier + immediate TMA issue (no cross-warp deps) ----
    if (lane == 0) {
        asm volatile("mbarrier.init.shared::cta.b64 [%0], 1;" :: "r"(a_mbar) : "memory");
    }
    __syncwarp();
    if (full && lane == 0) {
        asm volatile("mbarrier.arrive.expect_tx.shared::cta.b64 _, [%0], %1;"
                     :: "r"(a_mbar), "r"(2 * WARP_BYTES) : "memory");
        asm volatile("cp.async.bulk.shared::cluster.global.mbarrier::complete_tx::bytes "
                     "[%0], [%1], %2, [%3];"
                     :: "r"(a_rep), "l"(rep + row0 * 7), "r"(WARP_BYTES), "r"(a_mbar) : "memory");
        asm volatile("cp.async.bulk.shared::cluster.global.mbarrier::complete_tx::bytes "
                     "[%0], [%1], %2, [%3];"
                     :: "r"(a_emo), "l"(emo + row0 * 7), "r"(WARP_BYTES), "r"(a_mbar) : "memory");
    }

    // ---- constants, computed redundantly by EVERY warp (benign identical races) ----
    {
        int idx = lane;
        #pragma unroll
        for (int h = 0; h < 2; ++h, idx += 32) {
            if (idx < 49) {
                int j = idx / 7, k = idx % 7;
                float acc = 0.f;
                #pragma unroll
                for (int i = 0; i < 7; ++i) acc = fmaf(WQ[i * 7 + j], WK[i * 7 + k], acc);
                sm.M[j * 8 + k] = acc;
            }
        }
        if (lane < 7) {
            float acc = 0.f;
            #pragma unroll
            for (int j = 0; j < 7; ++j) acc += WD[j * 7 + lane];
            sm.CW[lane] = acc;
        } else if (lane == 7) {
            float acc = 0.f;
            #pragma unroll
            for (int i = 0; i < 7; ++i) acc += bD[i];
            sm.CW[7] = acc;
        }
    }
    __syncwarp();   // own warp wrote ALL of M/CW -> visible to own lanes

    const float4* sM4  = (const float4*)sm.M;
    const float4  cc0  = ((const float4*)sm.CW)[0];
    const float4  cc1  = ((const float4*)sm.CW)[1];
    const float cw[7] = {cc0.x, cc0.y, cc0.z, cc0.w, cc1.x, cc1.y, cc1.z};
    const float cb = cc1.w;

    if (full) {
        // wait own warp's data
        asm volatile(
            "{\n\t.reg .pred P;\n\t"
            "W_%=:\n\t"
            "mbarrier.try_wait.parity.acquire.cta.shared::cta.b64 P, [%0], 0;\n\t"
            "@!P bra W_%=;\n\t}"
            :: "r"(a_mbar) : "memory");

        float* rb = &sm.rep[wid][0];
        float* eb = &sm.emo[wid][0];

        // 4 rows per lane: rows lane, lane+32, lane+64, lane+96 (stride-7 LDS, conflict-free)
        #pragma unroll
        for (int q = 0; q < 4; ++q) {
            const int base = (lane + q * 32) * 7;
            float r[7], e[7];
            #pragma unroll
            for (int j = 0; j < 7; ++j) { r[j] = rb[base + j]; e[j] = eb[base + j]; }

            float t[7];
            #pragma unroll
            for (int k = 0; k < 7; ++k) t[k] = 0.f;
            #pragma unroll
            for (int j = 0; j < 7; ++j) {
                float4 m0 = sM4[j * 2 + 0];
                float4 m1 = sM4[j * 2 + 1];
                float ej = e[j];
                t[0] = fmaf(ej, m0.x, t[0]);
                t[1] = fmaf(ej, m0.y, t[1]);
                t[2] = fmaf(ej, m0.z, t[2]);
                t[3] = fmaf(ej, m0.w, t[3]);
                t[4] = fmaf(ej, m1.x, t[4]);
                t[5] = fmaf(ej, m1.y, t[5]);
                t[6] = fmaf(ej, m1.z, t[6]);
            }
            // softmax without max-subtraction (|raw| << 88: exp safe)
            float p[7], sum = 0.f;
            #pragma unroll
            for (int k = 0; k < 7; ++k) { p[k] = __expf(r[k] * t[k]); sum += p[k]; }
            float inv = __fdividef(1.f, sum);

            #pragma unroll
            for (int k = 0; k < 7; ++k) {
                float sv = p[k] * inv;
                float s3 = sv * sv * sv;
                float d  = fmaf(s3, cw[k], cb);
                d = fminf(1.f, fmaxf(-1.f, d));
                rb[base + k] = r[k] + d;       // in-place result
            }
        }

        // make this warp's STS visible to the async proxy, then warp-private bulk store
        asm volatile("fence.proxy.async.shared::cta;" ::: "memory");
        __syncwarp();
        if (lane == 0) {
            asm volatile("cp.async.bulk.global.shared::cta.bulk_group [%0], [%1], %2;"
                         :: "l"(out + row0 * 7), "r"(a_rep), "r"(WARP_BYTES) : "memory");
            asm volatile("cp.async.bulk.commit_group;" ::: "memory");
            asm volatile("cp.async.bulk.wait_group.read 0;" ::: "memory");
        }
    } else {
        // partial sub-tile (tail): direct global path, 4 rows per lane
        #pragma unroll
        for (int q = 0; q < 4; ++q) {
            long long row = row0 + lane + q * 32;
            if (row < (long long)nrows) {
                float r[7], e[7];
                #pragma unroll
                for (int j = 0; j < 7; ++j) { r[j] = rep[row * 7 + j]; e[j] = emo[row * 7 + j]; }
                float t[7];
                #pragma unroll
                for (int k = 0; k < 7; ++k) t[k] = 0.f;
                #pragma unroll
                for (int j = 0; j < 7; ++j) {
                    float ej = e[j];
                    #pragma unroll
                    for (int k = 0; k < 7; ++k) t[k] = fmaf(ej, sm.M[j * 8 + k], t[k]);
                }
                float p[7], sum = 0.f;
                #pragma unroll
                for (int k = 0; k < 7; ++k) { p[k] = __expf(r[k] * t[k]); sum += p[k]; }
                float inv = __fdividef(1.f, sum);
                #pragma unroll
                for (int k = 0; k < 7; ++k) {
                    float sv = p[k] * inv;
                    float s3 = sv * sv * sv;
                    float d  = fmaf(s3, cw[k], cb);
                    d = fminf(1.f, fmaxf(-1.f, d));
                    out[row * 7 + k] = r[k] + d;
                }
            }
        }
    }
}

extern "C" void kernel_launch(void* const* d_in, const int* in_sizes, int n_in,
                              void* d_out, int out_size)
{
    const float* rep = (const float*)d_in[0];
    const float* emo = (const float*)d_in[1];
    const float* WQ  = (const float*)d_in[2];
    const float* WK  = (const float*)d_in[3];
    const float* WD  = (const float*)d_in[4];
    const float* bD  = (const float*)d_in[5];
    float* out = (float*)d_out;

    int nrows = in_sizes[0] / 7;
    int grid  = (nrows + ROWS_PER_BLOCK - 1) / ROWS_PER_BLOCK;

    cudaFuncSetAttribute(emotion_kernel,
                         cudaFuncAttributeMaxDynamicSharedMemorySize, SMEM_BYTES);
    emotion_kernel<<<grid, THREADS, SMEM_BYTES>>>(rep, emo, WQ, WK, WD, bD, out, nrows);
}